// round 13
// baseline (speedup 1.0000x reference)
#include <cuda_runtime.h>
#include <cstdint>

// Idx2PixelLayer: bilinear gather of N=1e6 points from a 2048x2048x8 fp32 image.
// c = ((coord - 1) mod (dim - 4)) + 1   (non-negative mod, JAX semantics)
// out = w00*g(0,0) + w10*g(1,0) + w01*g(0,1) + w11*g(1,1)
//   w00=d0*d1, w10=(1-d0)*d1, w01=d0*(1-d1), w11=(1-d0)*(1-d1)
// Reference's off-mask is always false (c <= 2045 < 2048), so dropped.
//
// R12: minimal-overhead in-block binning. R9-R11 proved bin-major scheduling
// reliably cuts DRAM traffic 198 -> ~150MB (concurrent image window ~40MB is
// L2-resident, duplicate pixel hits dedup), but sweep/staging overhead kept
// eating the win. This version strips the sweep to: load x only (4B), cheap
// bin test (clamp((int)x)>>10; x<1 wrap points land in bin 0, processed
// exactly once), ballot-compact POINT IDS ONLY into smem. The process phase
// re-reads coords[p] - p lies in this block's own 4KB coord chunk, L1-hot
// from the sweep - and runs the full fmod math once, with the proven
// 2-threads/point layout (lane pair = one 32B pixel sector per gather).

static constexpr int H = 2048;
static constexpr int W = 2048;
static constexpr int C = 8;

static constexpr int NBINS    = 2;
static constexpr int BINSHIFT = 10;     // 1024 rows per bin (64MB of image)
static constexpr int CHUNK    = 512;    // points per block sweep
static constexpr int THREADS  = 256;
static constexpr int CAP      = 384;    // smem slots (mean 256, sd ~11)

__global__ __launch_bounds__(THREADS)
void idx2pixel_binned(const float2* __restrict__ coords,
                      const float*  __restrict__ visible,
                      float* __restrict__ out,
                      int n, int nchunk)
{
    __shared__ int s_cnt;
    __shared__ int s_id[CAP];

    const int bin   = blockIdx.x / nchunk;   // bin-major: resident wave stays in one bin
    const int chunk = blockIdx.x % nchunk;
    const int tid   = threadIdx.x;
    const int lane  = tid & 31;
    const int p0    = chunk * CHUNK;
    const int RS    = W * C;

    if (tid == 0) s_cnt = 0;
    __syncthreads();

    const float* xs = reinterpret_cast<const float*>(coords);

    // ---- sweep: x-only load + cheap filter + ballot compaction of ids ----
    #pragma unroll
    for (int r = 0; r < CHUNK; r += THREADS) {
        int p = p0 + r + tid;
        bool act = (p < n);
        float x = act ? __ldg(xs + 2 * p) : 0.0f;

        // Cheap consistent bin: equals i0>>10 for x>=1; wrap cases -> bin 0.
        int bx = min(max((int)x, 0), H - 1);
        bool match = act && ((bx >> BINSHIFT) == bin);

        unsigned m = __ballot_sync(0xffffffffu, match);
        int alloc = 0;
        if (m) {
            int leader = __ffs(m) - 1;
            if (lane == leader) alloc = atomicAdd(&s_cnt, __popc(m));
            alloc = __shfl_sync(0xffffffffu, alloc, leader);
        }
        if (match) {
            int slot = alloc + __popc(m & ((1u << lane) - 1u));
            if (slot < CAP) s_id[slot] = p;
            else            s_id[0] = s_id[0];  // placeholder; overflow handled below
            // Overflow guard (statistically unreachable): process inline.
            if (slot >= CAP) {
                float2 xy = __ldg(coords + p);
                const float m0 = (float)(H - 4), m1 = (float)(W - 4);
                float c0 = fmodf(xy.x - 1.0f, m0); if (c0 < 0.0f) c0 += m0; c0 += 1.0f;
                float c1 = fmodf(xy.y - 1.0f, m1); if (c1 < 0.0f) c1 += m1; c1 += 1.0f;
                float f0 = floorf(c0), f1 = floorf(c1);
                float d0 = c0 - f0,  d1 = c1 - f1;
                int base = ((int)f0 * W + (int)f1) * C;
                float w00 = d0*d1, w10 = (1.0f-d0)*d1, w01 = d0*(1.0f-d1), w11 = (1.0f-d0)*(1.0f-d1);
                #pragma unroll
                for (int k = 0; k < 2; k++) {
                    const float4* q00 = reinterpret_cast<const float4*>(visible + base + 4*k);
                    const float4* q01 = reinterpret_cast<const float4*>(visible + base + 4*k + C);
                    const float4* q10 = reinterpret_cast<const float4*>(visible + base + 4*k + RS);
                    const float4* q11 = reinterpret_cast<const float4*>(visible + base + 4*k + RS + C);
                    float4 a00 = __ldg(q00), a01 = __ldg(q01), a10 = __ldg(q10), a11 = __ldg(q11);
                    float4 o;
                    o.x = w00*a00.x + w10*a10.x + w01*a01.x + w11*a11.x;
                    o.y = w00*a00.y + w10*a10.y + w01*a01.y + w11*a11.y;
                    o.z = w00*a00.z + w10*a10.z + w01*a01.z + w11*a11.z;
                    o.w = w00*a00.w + w10*a10.w + w01*a01.w + w11*a11.w;
                    __stcs(reinterpret_cast<float4*>(out + p * C + 4*k), o);
                }
            }
        }
    }
    __syncthreads();

    // ---- process: 2 threads/point; coords re-read (L1-hot); math once ----
    int cnt = min(s_cnt, CAP);
    int k = tid & 1;                       // channel half: floats [4k, 4k+4)
    const float m0 = (float)(H - 4), m1 = (float)(W - 4);

    for (int i = tid >> 1; i < cnt; i += THREADS / 2) {
        int p = s_id[i];
        float2 xy = __ldg(coords + p);     // within this block's 4KB chunk: L1 hit

        float c0 = fmodf(xy.x - 1.0f, m0); if (c0 < 0.0f) c0 += m0; c0 += 1.0f;
        float c1 = fmodf(xy.y - 1.0f, m1); if (c1 < 0.0f) c1 += m1; c1 += 1.0f;
        float f0 = floorf(c0), f1 = floorf(c1);
        float d0 = c0 - f0,  d1 = c1 - f1;
        int base = ((int)f0 * W + (int)f1) * C + 4 * k;

        const float4* q00 = reinterpret_cast<const float4*>(visible + base);
        const float4* q01 = reinterpret_cast<const float4*>(visible + base + C);
        const float4* q10 = reinterpret_cast<const float4*>(visible + base + RS);
        const float4* q11 = reinterpret_cast<const float4*>(visible + base + RS + C);

        float4 a00 = __ldg(q00);
        float4 a01 = __ldg(q01);
        float4 a10 = __ldg(q10);
        float4 a11 = __ldg(q11);

        float w00 = d0 * d1;
        float w10 = (1.0f - d0) * d1;
        float w01 = d0 * (1.0f - d1);
        float w11 = (1.0f - d0) * (1.0f - d1);

        float4 o;
        o.x = w00*a00.x + w10*a10.x + w01*a01.x + w11*a11.x;
        o.y = w00*a00.y + w10*a10.y + w01*a01.y + w11*a11.y;
        o.z = w00*a00.z + w10*a10.z + w01*a01.z + w11*a11.z;
        o.w = w00*a00.w + w10*a10.w + w01*a01.w + w11*a11.w;

        __stcs(reinterpret_cast<float4*>(out + p * C + 4 * k), o);
    }
}

extern "C" void kernel_launch(void* const* d_in, const int* in_sizes, int n_in,
                              void* d_out, int out_size)
{
    const float2* coords  = (const float2*)d_in[0];  // [N, 2] fp32
    const float*  visible = (const float*)d_in[1];   // [H, W, C] fp32
    float* out = (float*)d_out;                      // [N, C] fp32

    int n = in_sizes[0] / 2;   // number of points
    (void)n_in; (void)out_size;

    int nchunk = (n + CHUNK - 1) / CHUNK;            // 1954 for n=1e6
    int blocks = NBINS * nchunk;                     // bin-major grid
    idx2pixel_binned<<<blocks, THREADS>>>(coords, visible, out, n, nchunk);
}

// round 14
// speedup vs baseline: 1.2508x; 1.2508x over previous
#include <cuda_runtime.h>
#include <cstdint>

// Idx2PixelLayer: bilinear gather of N=1e6 points from a 2048x2048x8 fp32 image.
// c = ((coord - 1) mod (dim - 4)) + 1   (non-negative mod, JAX semantics)
// out = w00*g(0,0) + w10*g(1,0) + w01*g(0,1) + w11*g(1,1)
//   w00=d0*d1, w10=(1-d0)*d1, w01=d0*(1-d1), w11=(1-d0)*(1-d1)
// Reference's off-mask is always false (c <= 2045 < 2048), so dropped.
//
// R13: back to the simple champion (R2 shape) but with 256-bit gathers.
// sm_103 supports ld.global.nc.v8.b32 (LDG.256). A pixel's 8 channels are
// exactly 32B -> one v8 load per gathered pixel. 1 thread/point, 4 LDG.256
// front-batched: half the gather instructions/requests of the 2-thread
// scheme, full-sector requests, and 2x the per-warp in-flight gather bytes
// (deeper DRAM queue). ~50 regs still fits 32 warps/SM. Output is 32B
// contiguous per thread, consecutive threads adjacent -> coalesced STG.128x2
// streaming stores. (Binning abandoned: R9-R12 all lost more BW efficiency
// to phase structure than the ~45MB traffic saving was worth.)

static constexpr int H = 2048;
static constexpr int W = 2048;
static constexpr int C = 8;

struct Px {  // one pixel: 8 fp32 channels (32B)
    float v[8];
};

__device__ __forceinline__ Px ldg256(const float* p) {
    Px r;
    uint32_t a, b, c, d, e, f, g, h;
    asm volatile("ld.global.nc.v8.b32 {%0,%1,%2,%3,%4,%5,%6,%7}, [%8];"
                 : "=r"(a), "=r"(b), "=r"(c), "=r"(d),
                   "=r"(e), "=r"(f), "=r"(g), "=r"(h)
                 : "l"(p));
    r.v[0] = __uint_as_float(a); r.v[1] = __uint_as_float(b);
    r.v[2] = __uint_as_float(c); r.v[3] = __uint_as_float(d);
    r.v[4] = __uint_as_float(e); r.v[5] = __uint_as_float(f);
    r.v[6] = __uint_as_float(g); r.v[7] = __uint_as_float(h);
    return r;
}

__global__ __launch_bounds__(256)
void idx2pixel_kernel(const float2* __restrict__ coords,
                      const float*  __restrict__ visible,
                      float* __restrict__ out,
                      int n)
{
    int p = blockIdx.x * blockDim.x + threadIdx.x;
    if (p >= n) return;

    float2 xy = __ldcs(coords + p);

    const float m0 = (float)(H - 4);   // 2044
    const float m1 = (float)(W - 4);

    float c0 = fmodf(xy.x - 1.0f, m0); if (c0 < 0.0f) c0 += m0; c0 += 1.0f;
    float c1 = fmodf(xy.y - 1.0f, m1); if (c1 < 0.0f) c1 += m1; c1 += 1.0f;

    float f0 = floorf(c0);
    float f1 = floorf(c1);
    float d0 = c0 - f0;
    float d1 = c1 - f1;
    int   i0 = (int)f0;
    int   i1 = (int)f1;

    const int RS = W * C;
    int base = (i0 * W + i1) * C;

    // Four 256-bit gathers, front-batched for max MLP.
    Px a00 = ldg256(visible + base);            // g(0,0)
    Px a01 = ldg256(visible + base + C);        // g(0,1)
    Px a10 = ldg256(visible + base + RS);       // g(1,0)
    Px a11 = ldg256(visible + base + RS + C);   // g(1,1)

    float w00 = d0 * d1;
    float w10 = (1.0f - d0) * d1;
    float w01 = d0 * (1.0f - d1);
    float w11 = (1.0f - d0) * (1.0f - d1);

    float4 oa, ob;
    oa.x = w00*a00.v[0] + w10*a10.v[0] + w01*a01.v[0] + w11*a11.v[0];
    oa.y = w00*a00.v[1] + w10*a10.v[1] + w01*a01.v[1] + w11*a11.v[1];
    oa.z = w00*a00.v[2] + w10*a10.v[2] + w01*a01.v[2] + w11*a11.v[2];
    oa.w = w00*a00.v[3] + w10*a10.v[3] + w01*a01.v[3] + w11*a11.v[3];
    ob.x = w00*a00.v[4] + w10*a10.v[4] + w01*a01.v[4] + w11*a11.v[4];
    ob.y = w00*a00.v[5] + w10*a10.v[5] + w01*a01.v[5] + w11*a11.v[5];
    ob.z = w00*a00.v[6] + w10*a10.v[6] + w01*a01.v[6] + w11*a11.v[6];
    ob.w = w00*a00.v[7] + w10*a10.v[7] + w01*a01.v[7] + w11*a11.v[7];

    // 32B contiguous per thread; consecutive threads adjacent -> coalesced.
    __stcs(reinterpret_cast<float4*>(out + p * C), oa);
    __stcs(reinterpret_cast<float4*>(out + p * C) + 1, ob);
}

extern "C" void kernel_launch(void* const* d_in, const int* in_sizes, int n_in,
                              void* d_out, int out_size)
{
    const float2* coords  = (const float2*)d_in[0];  // [N, 2] fp32
    const float*  visible = (const float*)d_in[1];   // [H, W, C] fp32
    float* out = (float*)d_out;                      // [N, C] fp32

    int n = in_sizes[0] / 2;   // number of points
    (void)n_in; (void)out_size;

    int threads = 256;
    int blocks = (n + threads - 1) / threads;
    idx2pixel_kernel<<<blocks, threads>>>(coords, visible, out, n);
}